// round 16
// baseline (speedup 1.0000x reference)
#include <cuda_runtime.h>
#include <cuda_bf16.h>
#include <cstdint>

// MultiVariatePoly as a true GEMM over (j,k):
//   G[pt, i] = sum_{jk} W[i, jk] * v[pt, jk],  v = Py (x) Pz  (outer product, 100 vals)
//   out[pt]  = sum_i G[pt, i] * Px[i] + b
// bf16 split-2 in K: blocks (vh,Whi) (vl,Whi) (vh,Wlo), each padded to 112 cols
// -> K = 336 = 21 k16-steps; A/B store 2 blocks (224 cols), k-map reuses them.
// CTA = 64 points, 128 threads (warps 0-1 build vh / Whi+Wlo, warps 2-3 build vl).
// Loop: 2 ldmatrix.x4 + 2 HMMA per k-step, D accumulates in registers.
// Epilogue: 4 v2 Px loads + 8 FMA + quad shfl-reduce.

#define NP1 10
#define TPB 128
#define PTS 64
#define ACOLS 232             // bf16 cols per row: 2x112 blocks + 8 stride pad
#define ABYTES (ACOLS * 2)    // 464 B (116 words ≡ 20 mod 32: conflict-free ldmatrix)
#define PSTRF 18              // floats per Px row (10 + 6 zero + 2 pad)

typedef uint32_t u32;

__device__ __forceinline__ u32 smem_u32(const void* p) {
    u32 a;
    asm("{ .reg .u64 t; cvta.to.shared.u64 t, %1; cvt.u32.u64 %0, t; }" : "=r"(a) : "l"(p));
    return a;
}
__device__ __forceinline__ void ldmatrix_x4(u32* r, u32 addr) {
    asm volatile("ldmatrix.sync.aligned.m8n8.x4.shared.b16 {%0,%1,%2,%3}, [%4];"
                 : "=r"(r[0]), "=r"(r[1]), "=r"(r[2]), "=r"(r[3]) : "r"(addr));
}
__device__ __forceinline__ float2 lds_f32x2(u32 a) {
    float2 v; asm("ld.shared.v2.f32 {%0,%1}, [%2];" : "=f"(v.x), "=f"(v.y) : "r"(a)); return v;
}
__device__ __forceinline__ void sts128(u32 a, u32 r0, u32 r1, u32 r2, u32 r3) {
    asm volatile("st.shared.v4.b32 [%0], {%1,%2,%3,%4};" :: "r"(a), "r"(r0), "r"(r1), "r"(r2), "r"(r3) : "memory");
}
__device__ __forceinline__ void sts64(u32 a, u32 r0, u32 r1) {
    asm volatile("st.shared.v2.b32 [%0], {%1,%2};" :: "r"(a), "r"(r0), "r"(r1) : "memory");
}
__device__ __forceinline__ void mma_bf16(float& d0, float& d1, float& d2, float& d3,
                                         const u32* a, const u32* b) {
    asm volatile(
        "mma.sync.aligned.m16n8k16.row.col.f32.bf16.bf16.f32 "
        "{%0,%1,%2,%3}, {%4,%5,%6,%7}, {%8,%9}, {%0,%1,%2,%3};"
        : "+f"(d0), "+f"(d1), "+f"(d2), "+f"(d3)
        : "r"(a[0]), "r"(a[1]), "r"(a[2]), "r"(a[3]), "r"(b[0]), "r"(b[1]));
}
// pack two floats to bf16x2 (lo in low half)
__device__ __forceinline__ u32 cvt2(float lo, float hi) {
    u32 r; asm("cvt.rn.bf16x2.f32 %0, %1, %2;" : "=r"(r) : "f"(hi), "f"(lo)); return r;
}
// residual pair: bf16(lo - tofloat(h.lo)), bf16(hi - tofloat(h.hi))
__device__ __forceinline__ u32 resid2(float lo, float hi, u32 h) {
    float lf = __uint_as_float(h << 16);
    float hf = __uint_as_float(h & 0xFFFF0000u);
    return cvt2(lo - lf, hi - hf);
}

__device__ __forceinline__ void legendre1(float x, float P[NP1]) {
    P[0] = 1.0f;
    P[1] = x;
#pragma unroll
    for (int k = 1; k < NP1 - 1; k++) {
        const float c1 = (float)(2 * k + 1) / (float)(k + 1);
        const float c2 = -(float)k / (float)(k + 1);
        P[k + 1] = c1 * x * P[k] + c2 * P[k - 1];
    }
}

__global__ void __launch_bounds__(TPB, 5)
poly_gemm_kernel(const float* __restrict__ x, const float* __restrict__ W,
                 const float* __restrict__ bptr, float* __restrict__ out, int N) {
    __shared__ __align__(16) __nv_bfloat16 sA[PTS * ACOLS];  // 29 KB: v rows
    __shared__ __align__(16) __nv_bfloat16 sB[16 * ACOLS];   // 7.25 KB: W rows
    __shared__ __align__(16) float sP[PTS * PSTRF];          // 4.5 KB: Px rows

    const int tid = threadIdx.x;
    const int lane = tid & 31;
    const int wrp = tid >> 5;
    const u32 smA = smem_u32(sA);
    const u32 smB = smem_u32(sB);
    const u32 smP = smem_u32(sP);

    // ---- zero everything (pads must be 0) ----
    {
        float4 z4 = make_float4(0.f, 0.f, 0.f, 0.f);
        float4* a4 = (float4*)sA;
        float4* b4 = (float4*)sB;
        float4* p4 = (float4*)sP;
#pragma unroll
        for (int e = 0; e < 15; e++) { int q = e * TPB + tid; if (q < PTS * ACOLS / 8) a4[q] = z4; }
#pragma unroll
        for (int e = 0; e < 4; e++) { int q = e * TPB + tid; if (q < 16 * ACOLS / 8) b4[q] = z4; }
        { int q = tid; if (q < PTS * PSTRF / 4) p4[q] = z4; if (q + TPB < PTS * PSTRF / 4) p4[q + TPB] = z4; }
    }
    float bb = *bptr;
    __syncthreads();

    // ---- prologue: role 0 (warps 0-1) builds vh rows; role 1 (warps 2-3) vl rows ----
    const int role = tid >> 6;
    const int ptl = tid & 63;
    const int pglobal = blockIdx.x * PTS + ptl;
    const int pcl = (pglobal < N) ? pglobal : (N - 1);

    {
        float xx = x[3 * pcl + 0], yy = x[3 * pcl + 1], zz = x[3 * pcl + 2];
        float Py[NP1], Pz[NP1];
        legendre1(yy, Py);
        legendre1(zz, Pz);

        if (role == 0) {
            float Px[NP1];
            legendre1(xx, Px);
            u32 pb = smP + ptl * (PSTRF * 4);
#pragma unroll
            for (int k = 0; k < 5; k++)
                sts64(pb + k * 8, __float_as_uint(Px[2 * k]), __float_as_uint(Px[2 * k + 1]));
        }

        // v pairs -> 50 u32 (role0: bf16(v); role1: bf16 residual)
        u32 q[50];
#pragma unroll
        for (int j = 0; j < NP1; j++)
#pragma unroll
            for (int kk = 0; kk < 5; kk++) {
                float v0 = Py[j] * Pz[2 * kk];
                float v1 = Py[j] * Pz[2 * kk + 1];
                u32 h = cvt2(v0, v1);
                q[j * 5 + kk] = (role == 0) ? h : resid2(v0, v1, h);
            }
        u32 rb = smA + ptl * ABYTES + role * 224;  // block 0 (vh) or block 1 (vl)
#pragma unroll
        for (int e = 0; e < 12; e++)
            sts128(rb + e * 16, q[4 * e], q[4 * e + 1], q[4 * e + 2], q[4 * e + 3]);
        sts64(rb + 192, q[48], q[49]);
    }

    // ---- B rows: threads 0-9 -> Whi (block 0); threads 32-41 -> Wlo (block 1) ----
    if (tid < 10 || (tid >= 32 && tid < 42)) {
        int r = (tid < 10) ? tid : (tid - 32);
        int blk = (tid < 10) ? 0 : 1;
        const float* wr = W + r * 100;
        u32 q[50];
#pragma unroll
        for (int e = 0; e < 50; e++) {
            float w0 = wr[2 * e], w1 = wr[2 * e + 1];
            u32 h = cvt2(w0, w1);
            q[e] = blk ? resid2(w0, w1, h) : h;
        }
        u32 rb = smB + r * ABYTES + blk * 224;
#pragma unroll
        for (int e = 0; e < 12; e++)
            sts128(rb + e * 16, q[4 * e], q[4 * e + 1], q[4 * e + 2], q[4 * e + 3]);
        sts64(rb + 192, q[48], q[49]);
    }
    __syncthreads();

    // ---- GEMM: warp wrp owns m16 tile (points 16*wrp .. +15); n16 = 2 n8 tiles ----
    // A ldmatrix.x4: m0 rows0-7 k-lo | m1 rows8-15 k-lo | m2 rows0-7 k-hi | m3 rows8-15 k-hi
    const u32 aband = smA + (16 * wrp + (lane & 7) + (((lane >> 3) & 1) << 3)) * ABYTES
                      + ((lane >> 4) & 1) * 16;
    // B ldmatrix.x4: m0 (n0-7,k-lo) | m1 (n0-7,k-hi) | m2 (n8-15,k-lo) | m3 (n8-15,k-hi)
    const u32 bband = smB + ((lane & 7) + ((lane >> 4) & 1) * 8) * ABYTES
                      + ((lane >> 3) & 1) * 16;

    float d0 = 0.f, d1 = 0.f, d2 = 0.f, d3 = 0.f;      // nt0 (i cols 0-7)
    float e0 = 0.f, e1 = 0.f, e2 = 0.f, e3 = 0.f;      // nt1 (i cols 8-15)

#pragma unroll
    for (int s = 0; s < 21; s++) {
        // k-map: blocks (vh,Whi) s=0..6, (vl,Whi) s=7..13, (vh,Wlo) s=14..20
        const int ka = (s < 7) ? s * 16 : (s < 14) ? 112 + (s - 7) * 16 : (s - 14) * 16;
        const int kb = (s < 7) ? s * 16 : (s < 14) ? (s - 7) * 16 : 112 + (s - 14) * 16;
        u32 aq[4], bq[4];
        ldmatrix_x4(aq, aband + ka * 2);
        ldmatrix_x4(bq, bband + kb * 2);
        mma_bf16(d0, d1, d2, d3, aq, bq);       // n8 tile 0 (rows i 0-7)
        mma_bf16(e0, e1, e2, e3, aq, bq + 2);   // n8 tile 1 (rows i 8-15)
    }

    // ---- epilogue: fold with Px, quad shfl-reduce ----
    const int rg = lane >> 2;
    const int i0 = 2 * (lane & 3);
    const u32 pr0 = smP + (16 * wrp + rg) * (PSTRF * 4);
    const u32 pr1 = pr0 + 8 * (PSTRF * 4);
    float2 a0 = lds_f32x2(pr0 + i0 * 4);        // Px[i0], Px[i0+1]
    float2 a1 = lds_f32x2(pr0 + (8 + i0) * 4);  // Px[i0+8..] (zeros beyond 9)
    float2 b0 = lds_f32x2(pr1 + i0 * 4);
    float2 b1 = lds_f32x2(pr1 + (8 + i0) * 4);

    float acc0 = d0 * a0.x + d1 * a0.y + e0 * a1.x + e1 * a1.y;   // point rg
    float acc1 = d2 * b0.x + d3 * b0.y + e2 * b1.x + e3 * b1.y;   // point rg+8

    acc0 += __shfl_xor_sync(0xFFFFFFFFu, acc0, 1);
    acc0 += __shfl_xor_sync(0xFFFFFFFFu, acc0, 2);
    acc1 += __shfl_xor_sync(0xFFFFFFFFu, acc1, 1);
    acc1 += __shfl_xor_sync(0xFFFFFFFFu, acc1, 2);

    if ((lane & 3) == 0) {
        int p0 = blockIdx.x * PTS + 16 * wrp + rg;
        if (p0 < N) out[p0] = acc0 + bb;
        if (p0 + 8 < N) out[p0 + 8] = acc1 + bb;
    }
}

extern "C" void kernel_launch(void* const* d_in, const int* in_sizes, int n_in,
                              void* d_out, int out_size) {
    int ib = -1, ix = -1, iw = -1;
    int max_sz = -1;
    for (int i = 0; i < n_in; i++) {
        if (in_sizes[i] == 1 && ib < 0) ib = i;
        else if (in_sizes[i] > max_sz) { max_sz = in_sizes[i]; ix = i; }
    }
    for (int i = 0; i < n_in; i++) {
        if (i != ib && i != ix) { iw = i; break; }
    }

    const float* x = (const float*)d_in[ix];
    const float* W = (const float*)d_in[iw];
    const float* b = (const float*)d_in[ib];
    float* out = (float*)d_out;

    int N = in_sizes[ix] / 3;
    int grid = (N + PTS - 1) / PTS;  // 64 points per CTA

    poly_gemm_kernel<<<grid, TPB>>>(x, W, b, out, N);
}

// round 17
// speedup vs baseline: 1.6523x; 1.6523x over previous
#include <cuda_runtime.h>
#include <cuda_bf16.h>
#include <cstdint>

// MultiVariatePoly via mma.sync (HMMA) bf16 split-2 GEMM, fused epilogue.
// Per 128-point CTA: D[pt, f(i,j)] = A[128,32] @ B[104,32]^T
//   A row (point):   [Zhi(10) | Zlo(10) | Zhi(10) | 0 0]
//   B row (feature): [Whi(10) | Whi(10) | Wlo(10) | 0 0]
// Coefficients Px[i]*Py[j] applied to D fragments in the mma loop; quad
// shfl-reduce; one barrier; 29 KB smem.
// R17 = R15 + __launch_bounds__(128,8) (regs<=64 -> 7 CTAs/SM) + explicit
// mt-interleaved mma issue (4 mma, then 12 loads, then folds).

#define NP1 10
#define TPB 128
#define ASTR 40    // bf16 per A/B row (80 B)
#define BROWS 104  // 13 n8-tiles
#define PSTR 20    // floats per sP row: Px[10] | Py[10]

typedef uint32_t u32;

__device__ __forceinline__ u32 smem_u32(const void* p) {
    u32 a;
    asm("{ .reg .u64 t; cvta.to.shared.u64 t, %1; cvt.u32.u64 %0, t; }" : "=r"(a) : "l"(p));
    return a;
}
__device__ __forceinline__ void ldmatrix_x4(u32* r, u32 addr) {
    asm volatile("ldmatrix.sync.aligned.m8n8.x4.shared.b16 {%0,%1,%2,%3}, [%4];"
                 : "=r"(r[0]), "=r"(r[1]), "=r"(r[2]), "=r"(r[3]) : "r"(addr));
}
__device__ __forceinline__ float lds_f32(u32 a) {
    float v; asm("ld.shared.f32 %0, [%1];" : "=f"(v) : "r"(a)); return v;
}
__device__ __forceinline__ float2 lds_f32x2(u32 a) {
    float2 v; asm("ld.shared.v2.f32 {%0,%1}, [%2];" : "=f"(v.x), "=f"(v.y) : "r"(a)); return v;
}
__device__ __forceinline__ void mma_bf16(float& d0, float& d1, float& d2, float& d3,
                                         const u32* a, const u32* b) {
    asm volatile(
        "mma.sync.aligned.m16n8k16.row.col.f32.bf16.bf16.f32 "
        "{%0,%1,%2,%3}, {%4,%5,%6,%7}, {%8,%9}, {%0,%1,%2,%3};"
        : "+f"(d0), "+f"(d1), "+f"(d2), "+f"(d3)
        : "r"(a[0]), "r"(a[1]), "r"(a[2]), "r"(a[3]), "r"(b[0]), "r"(b[1]));
}

__device__ __forceinline__ void legendre1(float x, float P[NP1]) {
    P[0] = 1.0f;
    P[1] = x;
#pragma unroll
    for (int k = 1; k < NP1 - 1; k++) {
        const float c1 = (float)(2 * k + 1) / (float)(k + 1);
        const float c2 = -(float)k / (float)(k + 1);
        P[k + 1] = c1 * x * P[k] + c2 * P[k - 1];
    }
}

__global__ void __launch_bounds__(TPB, 8)
poly_mma_kernel(const float* __restrict__ x, const float* __restrict__ W,
                const float* __restrict__ bptr, float* __restrict__ out, int N) {
    __shared__ __align__(16) __nv_bfloat16 sA[128 * ASTR];    // 10 KB
    __shared__ __align__(16) __nv_bfloat16 sB[BROWS * ASTR];  //  8.1 KB
    __shared__ __align__(8) float sP[128 * PSTR];             // 10 KB: Px|Py per point

    const int tid = threadIdx.x;
    const int lane = tid & 31;
    const int wrp = tid >> 5;
    const u32 smA = smem_u32(sA);
    const u32 smB = smem_u32(sB);
    const u32 smP = smem_u32(sP);

    // ---- per-point setup ----
    int p = blockIdx.x * TPB + tid;
    int pc = (p < N) ? p : (N - 1);
    float x0 = x[3 * pc + 0], x1 = x[3 * pc + 1], x2 = x[3 * pc + 2];
    float bb = *bptr;

    {
        float Px[NP1], Py[NP1], Pz[NP1];
        legendre1(x0, Px);
        legendre1(x1, Py);
        legendre1(x2, Pz);

        float2* prow = reinterpret_cast<float2*>(sP + tid * PSTR);
#pragma unroll
        for (int k = 0; k < 5; k++) prow[k] = make_float2(Px[2 * k], Px[2 * k + 1]);
#pragma unroll
        for (int k = 0; k < 5; k++) prow[5 + k] = make_float2(Py[2 * k], Py[2 * k + 1]);

        __nv_bfloat16 zh[NP1], zl[NP1];
#pragma unroll
        for (int k = 0; k < NP1; k++) {
            zh[k] = __float2bfloat16(Pz[k]);
            zl[k] = __float2bfloat16(Pz[k] - __bfloat162float(zh[k]));
        }
        __nv_bfloat162* row = reinterpret_cast<__nv_bfloat162*>(sA + tid * ASTR);
#pragma unroll
        for (int cc = 0; cc < 5; cc++) {
            __nv_bfloat162 v; v.x = zh[2 * cc]; v.y = zh[2 * cc + 1];
            row[cc] = v;
        }
#pragma unroll
        for (int cc = 0; cc < 5; cc++) {
            __nv_bfloat162 v; v.x = zl[2 * cc]; v.y = zl[2 * cc + 1];
            row[5 + cc] = v;
        }
#pragma unroll
        for (int cc = 0; cc < 5; cc++) {
            __nv_bfloat162 v; v.x = zh[2 * cc]; v.y = zh[2 * cc + 1];
            row[10 + cc] = v;
        }
        __nv_bfloat162 z2; z2.x = __float2bfloat16(0.f); z2.y = z2.x;
        row[15] = z2;  // cols 30,31 must be 0 for ldmatrix reads
    }

    // ---- B row (feature tid): [whi | whi | wlo | 0 0]; rows 100..103 zero ----
    if (tid < BROWS) {
        __nv_bfloat162* row = reinterpret_cast<__nv_bfloat162*>(sB + tid * ASTR);
        if (tid < 100) {
            const float* wr = W + 10 * tid;
            __nv_bfloat16 wh[NP1], wl[NP1];
#pragma unroll
            for (int k = 0; k < NP1; k++) {
                float w = wr[k];
                wh[k] = __float2bfloat16(w);
                wl[k] = __float2bfloat16(w - __bfloat162float(wh[k]));
            }
#pragma unroll
            for (int cc = 0; cc < 5; cc++) {
                __nv_bfloat162 v; v.x = wh[2 * cc]; v.y = wh[2 * cc + 1];
                row[cc] = v;
                row[5 + cc] = v;
            }
#pragma unroll
            for (int cc = 0; cc < 5; cc++) {
                __nv_bfloat162 v; v.x = wl[2 * cc]; v.y = wl[2 * cc + 1];
                row[10 + cc] = v;
            }
            __nv_bfloat162 z2; z2.x = __float2bfloat16(0.f); z2.y = z2.x;
            row[15] = z2;
        } else {
            __nv_bfloat162 z2; z2.x = __float2bfloat16(0.f); z2.y = z2.x;
#pragma unroll
            for (int cc = 0; cc < 16; cc++) row[cc] = z2;
        }
    }
    __syncthreads();  // the only barrier

    // ---- A fragments (verified mapping) ----
    u32 afr[2][2][4];
    {
        int m = lane >> 3, ri = lane & 7;
        int arow_base = wrp * 32 + ri + ((m & 1) << 3);
        int acol_off = (m & 2) ? 8 : 0;
#pragma unroll
        for (int mt = 0; mt < 2; mt++)
#pragma unroll
            for (int ks = 0; ks < 2; ks++) {
                u32 ad = smA + ((arow_base + 16 * mt) * ASTR + ks * 16 + acol_off) * 2;
                ldmatrix_x4(afr[mt][ks], ad);
            }
    }

    // B ldmatrix.x4 lane->addr: matrix m = lane>>3 at bf16-col 8m, row n0 + lane&7.
    const u32 browband = smB + ((lane & 7) * ASTR + 8 * (lane >> 3)) * 2;

    // Precomputed sP row addresses for the 4 points this thread's fragments touch.
    const int rg = wrp * 32 + (lane >> 2);
    const u32 pb00 = smP + (rg + 0) * (PSTR * 4);
    const u32 pb01 = smP + (rg + 8) * (PSTR * 4);
    const u32 pb10 = smP + (rg + 16) * (PSTR * 4);
    const u32 pb11 = smP + (rg + 24) * (PSTR * 4);

    const int dlo = 2 * (lane & 3);  // feature offset within n8-tile (even)

    float acc00 = 0.f, acc01 = 0.f, acc10 = 0.f, acc11 = 0.f;

#pragma unroll
    for (int nt = 0; nt < 13; nt++) {
        u32 bq[4];
        ldmatrix_x4(bq, browband + nt * (8 * ASTR * 2));

        int f0 = nt * 8 + dlo;
        int i = f0 / 10;           // ==10 only on pad lanes (D==0 there)
        int j0 = f0 - 10 * i;
        u32 oi4 = (u32)(i * 4);
        u32 oj4 = (u32)((10 + j0) * 4);

        // --- issue all 4 mma first (both mt tiles) ---
        float d0 = 0.f, d1 = 0.f, d2 = 0.f, d3 = 0.f;   // mt 0
        float g0 = 0.f, g1 = 0.f, g2 = 0.f, g3 = 0.f;   // mt 1
        mma_bf16(d0, d1, d2, d3, afr[0][0], bq);
        mma_bf16(g0, g1, g2, g3, afr[1][0], bq);
        mma_bf16(d0, d1, d2, d3, afr[0][1], bq + 2);
        mma_bf16(g0, g1, g2, g3, afr[1][1], bq + 2);

        // --- then all coefficient loads ---
        float px00 = lds_f32(pb00 + oi4);
        float px01 = lds_f32(pb01 + oi4);
        float px10 = lds_f32(pb10 + oi4);
        float px11 = lds_f32(pb11 + oi4);
        float2 py00 = lds_f32x2(pb00 + oj4);
        float2 py01 = lds_f32x2(pb01 + oj4);
        float2 py10 = lds_f32x2(pb10 + oj4);
        float2 py11 = lds_f32x2(pb11 + oj4);

        // --- then the folds ---
        acc00 = fmaf(px00, fmaf(d1, py00.y, d0 * py00.x), acc00);
        acc01 = fmaf(px01, fmaf(d3, py01.y, d2 * py01.x), acc01);
        acc10 = fmaf(px10, fmaf(g1, py10.y, g0 * py10.x), acc10);
        acc11 = fmaf(px11, fmaf(g3, py11.y, g2 * py11.x), acc11);
    }

    // ---- reduce across the 4 lanes of each quad ----
    acc00 += __shfl_xor_sync(0xFFFFFFFFu, acc00, 1);
    acc00 += __shfl_xor_sync(0xFFFFFFFFu, acc00, 2);
    acc01 += __shfl_xor_sync(0xFFFFFFFFu, acc01, 1);
    acc01 += __shfl_xor_sync(0xFFFFFFFFu, acc01, 2);
    acc10 += __shfl_xor_sync(0xFFFFFFFFu, acc10, 1);
    acc10 += __shfl_xor_sync(0xFFFFFFFFu, acc10, 2);
    acc11 += __shfl_xor_sync(0xFFFFFFFFu, acc11, 1);
    acc11 += __shfl_xor_sync(0xFFFFFFFFu, acc11, 2);

    if ((lane & 3) == 0) {
        int p0 = blockIdx.x * TPB + rg;
        if (p0 < N) out[p0] = acc00 + bb;
        if (p0 + 8 < N) out[p0 + 8] = acc01 + bb;
        if (p0 + 16 < N) out[p0 + 16] = acc10 + bb;
        if (p0 + 24 < N) out[p0 + 24] = acc11 + bb;
    }
}

extern "C" void kernel_launch(void* const* d_in, const int* in_sizes, int n_in,
                              void* d_out, int out_size) {
    int ib = -1, ix = -1, iw = -1;
    int max_sz = -1;
    for (int i = 0; i < n_in; i++) {
        if (in_sizes[i] == 1 && ib < 0) ib = i;
        else if (in_sizes[i] > max_sz) { max_sz = in_sizes[i]; ix = i; }
    }
    for (int i = 0; i < n_in; i++) {
        if (i != ib && i != ix) { iw = i; break; }
    }

    const float* x = (const float*)d_in[ix];
    const float* W = (const float*)d_in[iw];
    const float* b = (const float*)d_in[ib];
    float* out = (float*)d_out;

    int N = in_sizes[ix] / 3;
    int grid = (N + TPB - 1) / TPB;  // 128 points per CTA

    poly_mma_kernel<<<grid, TPB>>>(x, W, b, out, N);
}